// round 17
// baseline (speedup 1.0000x reference)
#include <cuda_runtime.h>
#include <cuda_fp16.h>
#include <math.h>
#include <stdint.h>

#define D     128
#define NMAX  50000
#define EMAX  1600000
#define THREADS 256
#define BK2   64     // K per chunk (4 x k16 mma steps)
#define SAH   72     // per-chunk A/B smem stride (halves): (4g+tig)%32 bijective
#define SHH   136    // full-K row stride (halves): (4g+tig)%32 bijective
#define ABUF_H (128 * SAH)   // 9216 halves = 18432 B
#define BBUF_H (128 * SAH)
#define FULLA_H (128 * SHH)  // 17408 halves = 34816 B (full-K tile)

// -------- device scratch --------
__device__ float  g_x[NMAX * D];       // fp32 x (epilogue math)
__device__ __half g_xh[NMAX * D];      // fp16 x (gather + gate A input)
__device__ __half g_xinh[NMAX * D];    // fp16 x_in
__device__ __half g_outh[NMAX * D];    // fp16 out
__device__ float  g_z[NMAX * D];       // fp32 z
__device__ __half g_rxh[NMAX * D];     // fp16 r*x
__device__ __half g_wh[10 * D * D];    // fp16 weights, TRANSPOSED [n][k]
__device__ int    g_cnt[NMAX];
__device__ int    g_start[NMAX + 1];
__device__ int    g_cur[NMAX];
__device__ int2   g_edges[EMAX];

__device__ __forceinline__ float sigf(float x) { return 1.0f / (1.0f + expf(-x)); }

__device__ __forceinline__ void mma_f16(float c[4],
                                        uint32_t a0, uint32_t a1, uint32_t a2, uint32_t a3,
                                        uint32_t b0, uint32_t b1) {
    asm volatile(
        "mma.sync.aligned.m16n8k16.row.col.f32.f16.f16.f32 "
        "{%0,%1,%2,%3}, {%4,%5,%6,%7}, {%8,%9}, {%0,%1,%2,%3};"
        : "+f"(c[0]), "+f"(c[1]), "+f"(c[2]), "+f"(c[3])
        : "r"(a0), "r"(a1), "r"(a2), "r"(a3), "r"(b0), "r"(b1));
}

// ---- cp.async helpers ----
__device__ __forceinline__ void cp16(void* dst_smem, const void* src, bool pred) {
    uint32_t dst = (uint32_t)__cvta_generic_to_shared(dst_smem);
    int sz = pred ? 16 : 0;
    asm volatile("cp.async.ca.shared.global [%0], [%1], 16, %2;\n"
                 :: "r"(dst), "l"(src), "r"(sz));
}
__device__ __forceinline__ void cp_commit() {
    asm volatile("cp.async.commit_group;\n");
}
template <int N>
__device__ __forceinline__ void cp_wait() {
    asm volatile("cp.async.wait_group %0;\n" :: "n"(N));
}

// A chunk [row0..+128) x [k0..+64) halves -> Abuf[row][k], stride SAH
__device__ __forceinline__ void cpA16(const __half* __restrict__ A, int row0, int Nrows,
                                      int k0, __half* Abuf, int tid) {
#pragma unroll
    for (int q2 = 0; q2 < 4; ++q2) {
        int idx = tid + q2 * 256;
        int row = idx >> 3;
        int q   = idx & 7;
        cp16(Abuf + row * SAH + q * 8,
             A + (size_t)(row0 + row) * D + k0 + q * 8,
             row0 + row < Nrows);
    }
}

// W chunk (transposed weights [n][k]) [0..128)n x [k0..+64) -> Bbuf[n][k]
__device__ __forceinline__ void cpB16(const __half* __restrict__ Wt, int k0,
                                      __half* Bbuf, int tid) {
#pragma unroll
    for (int q2 = 0; q2 < 4; ++q2) {
        int idx = tid + q2 * 256;
        int n = idx >> 3;
        int q = idx & 7;
        cp16(Bbuf + n * SAH + q * 8, Wt + (size_t)n * D + k0 + q * 8, true);
    }
}

// ---- mma over one 64-k chunk (4 x k16); A row-major stride sa, base k offset ak0 ----
__device__ __forceinline__ void mma_chunk16(const __half* Ar, int sa, int ak0,
                                            const __half* Bs,
                                            int m_base, int n_base, int g, int tig,
                                            float acc[2][8][4]) {
#pragma unroll
    for (int ks = 0; ks < 4; ++ks) {
        int ka = ak0 + ks * 16 + 2 * tig;
        int kb = ks * 16 + 2 * tig;
        uint32_t afr[2][4];
#pragma unroll
        for (int mt = 0; mt < 2; ++mt) {
            const __half* p0 = Ar + (m_base + mt * 16 + g) * sa + ka;
            const __half* p1 = p0 + 8 * sa;
            afr[mt][0] = *reinterpret_cast<const uint32_t*>(p0);
            afr[mt][1] = *reinterpret_cast<const uint32_t*>(p1);
            afr[mt][2] = *reinterpret_cast<const uint32_t*>(p0 + 8);
            afr[mt][3] = *reinterpret_cast<const uint32_t*>(p1 + 8);
        }
#pragma unroll
        for (int nt = 0; nt < 8; ++nt) {
            const __half* pb = Bs + (n_base + nt * 8 + g) * SAH + kb;
            uint32_t b0 = *reinterpret_cast<const uint32_t*>(pb);
            uint32_t b1 = *reinterpret_cast<const uint32_t*>(pb + 8);
            mma_f16(acc[0][nt], afr[0][0], afr[0][1], afr[0][2], afr[0][3], b0, b1);
            mma_f16(acc[1][nt], afr[1][0], afr[1][1], afr[1][2], afr[1][3], b0, b1);
        }
    }
}

// Dual-GEMM accumulate (4 chunks of 64 k), 2-stage cp.async (R12-proven).
__device__ __forceinline__ void dual_gemm_h(const __half* A1, const __half* W1t,
                                            const __half* A2, const __half* W2t,
                                            __half* smA, __half* smB,
                                            int row0, int Nrows, int tid,
                                            int m_base, int n_base, int g, int tig,
                                            float acc[2][8][4]) {
    const __half* Aarr[2] = {A1, A2};
    const __half* Warr[2] = {W1t, W2t};
    __half* Ab[2] = {smA, smA + ABUF_H};
    __half* Bb[2] = {smB, smB + BBUF_H};

    cpA16(Aarr[0], row0, Nrows, 0, Ab[0], tid);
    cpB16(Warr[0], 0, Bb[0], tid);
    cp_commit();
#pragma unroll 1
    for (int t = 0; t < 4; ++t) {
        if (t < 3) {
            int tp = t + 1;
            cpA16(Aarr[tp >> 1], row0, Nrows, (tp & 1) * BK2, Ab[tp & 1], tid);
            cpB16(Warr[tp >> 1], (tp & 1) * BK2, Bb[tp & 1], tid);
            cp_commit();
            cp_wait<1>();
        } else {
            cp_wait<0>();
        }
        __syncthreads();
        mma_chunk16(Ab[t & 1], SAH, 0, Bb[t & 1], m_base, n_base, g, tig, acc);
        __syncthreads();
    }
}

// ===========================================================================
// mlp1: fused 2-layer MLP, A from gmem (R12-proven), dual fp32+fp16 output.
// ===========================================================================
__global__ void __launch_bounds__(THREADS, 2)
mlp1_mma_kernel(const __half* __restrict__ A,
                const __half* __restrict__ W1t, const float* __restrict__ b1,
                const __half* __restrict__ W2t, const float* __restrict__ b2,
                float* __restrict__ O, __half* __restrict__ OH, int Nrows)
{
    extern __shared__ __half smh[];
    __half* Ab[2] = {smh, smh + ABUF_H};
    __half* Bb[2] = {smh + 2 * ABUF_H, smh + 2 * ABUF_H + BBUF_H};
    __half* Hs = smh + 2 * ABUF_H + 2 * BBUF_H;

    int tid  = threadIdx.x;
    int warp = tid >> 5;
    int lane = tid & 31;
    int g    = lane >> 2;
    int tig  = lane & 3;
    int m_base = (warp >> 1) * 32;
    int n_base = (warp & 1) * 64;
    int row0 = blockIdx.x * 128;

    float acc[2][8][4];
#pragma unroll
    for (int mt = 0; mt < 2; ++mt)
#pragma unroll
        for (int nt = 0; nt < 8; ++nt)
#pragma unroll
            for (int i = 0; i < 4; ++i) acc[mt][nt][i] = 0.f;

    cpA16(A, row0, Nrows, 0, Ab[0], tid);
    cpB16(W1t, 0, Bb[0], tid);
    cp_commit();
#pragma unroll 1
    for (int kc = 0; kc < 2; ++kc) {
        if (kc < 1) {
            cpA16(A, row0, Nrows, BK2, Ab[1], tid);
            cpB16(W1t, BK2, Bb[1], tid);
            cp_commit();
            cp_wait<1>();
        } else {
            cp_wait<0>();
        }
        __syncthreads();
        mma_chunk16(Ab[kc & 1], SAH, 0, Bb[kc & 1], m_base, n_base, g, tig, acc);
        __syncthreads();
    }

    cpB16(W2t, 0, Bb[0], tid);
    cp_commit();

#pragma unroll
    for (int nt = 0; nt < 8; ++nt) {
        int col = n_base + nt * 8 + 2 * tig;
        float bx = __ldg(&b1[col]);
        float by = __ldg(&b1[col + 1]);
#pragma unroll
        for (int mt = 0; mt < 2; ++mt) {
#pragma unroll
            for (int h = 0; h < 2; ++h) {
                int row = m_base + mt * 16 + g + h * 8;
                float tx = fmaxf(acc[mt][nt][2 * h]     + bx, 0.f);
                float ty = fmaxf(acc[mt][nt][2 * h + 1] + by, 0.f);
                *reinterpret_cast<__half2*>(Hs + row * SHH + col) =
                    __float22half2_rn(make_float2(tx, ty));
                acc[mt][nt][2 * h] = 0.f;
                acc[mt][nt][2 * h + 1] = 0.f;
            }
        }
    }
    __syncthreads();

#pragma unroll 1
    for (int kc = 0; kc < 2; ++kc) {
        if (kc < 1) {
            cpB16(W2t, BK2, Bb[1], tid);
            cp_commit();
            cp_wait<1>();
        } else {
            cp_wait<0>();
        }
        __syncthreads();
        mma_chunk16(Hs, SHH, kc * BK2, Bb[kc & 1], m_base, n_base, g, tig, acc);
        __syncthreads();
    }

#pragma unroll
    for (int nt = 0; nt < 8; ++nt) {
        int col = n_base + nt * 8 + 2 * tig;
        float2 bb = make_float2(__ldg(&b2[col]), __ldg(&b2[col + 1]));
#pragma unroll
        for (int mt = 0; mt < 2; ++mt) {
#pragma unroll
            for (int h = 0; h < 2; ++h) {
                int row = row0 + m_base + mt * 16 + g + h * 8;
                if (row >= Nrows) continue;
                float vx = acc[mt][nt][2 * h]     + bb.x;
                float vy = acc[mt][nt][2 * h + 1] + bb.y;
                *reinterpret_cast<float2*>(&O[(size_t)row * D + col]) =
                    make_float2(vx, vy);
                *reinterpret_cast<__half2*>(&OH[(size_t)row * D + col]) =
                    __float22half2_rn(make_float2(vx, vy));
            }
        }
    }
}

// ===========================================================================
// mlp2agg: GATHER fused with 2-layer MLP.
// Phase G gathers into Asm at FULL-K stride SHH (fix for R16's SAH bug).
// ===========================================================================
__global__ void __launch_bounds__(THREADS, 2)
mlp2agg_mma_kernel(const __half* __restrict__ xh,
                   const __half* __restrict__ W1t, const float* __restrict__ b1,
                   const __half* __restrict__ W2t, const float* __restrict__ b2,
                   __half* __restrict__ OH, int Nrows)
{
    extern __shared__ __half smh[];
    __half* Asm = smh;                                // 128*SHH (full-K tile)
    __half* Bb[2] = {smh + FULLA_H, smh + FULLA_H + BBUF_H};
    __half* Hs = smh + FULLA_H + 2 * BBUF_H;          // 128*SHH

    int tid  = threadIdx.x;
    int warp = tid >> 5;
    int lane = tid & 31;
    int g    = lane >> 2;
    int tig  = lane & 3;
    int m_base = (warp >> 1) * 32;
    int n_base = (warp & 1) * 64;
    int row0 = blockIdx.x * 128;

    // prefetch W1 both chunks while gathering
    cpB16(W1t, 0, Bb[0], tid);
    cp_commit();
    cpB16(W1t, BK2, Bb[1], tid);
    cp_commit();

    // ---- Phase G: gather 16 rows per warp into Asm (stride SHH) ----
    {
        const uint2* x2 = reinterpret_cast<const uint2*>(xh);
#pragma unroll 1
        for (int r = 0; r < 16; ++r) {
            int row = warp * 16 + r;
            int node = row0 + row;
            float4 acc4 = make_float4(0.f, 0.f, 0.f, 0.f);
            if (node < Nrows) {
                int s = __ldg(&g_start[node]);
                int t = __ldg(&g_start[node + 1]);
                int j = s;
                for (; j + 8 <= t; j += 8) {
                    int2 ee[8];
                    uint2 uu[8];
#pragma unroll
                    for (int q = 0; q < 8; ++q) ee[q] = __ldg(&g_edges[j + q]);
#pragma unroll
                    for (int q = 0; q < 8; ++q) uu[q] = x2[(size_t)ee[q].x * 32 + lane];
#pragma unroll
                    for (int q = 0; q < 8; ++q) {
                        float v = __int_as_float(ee[q].y);
                        float2 a = __half22float2(*reinterpret_cast<__half2*>(&uu[q].x));
                        float2 b = __half22float2(*reinterpret_cast<__half2*>(&uu[q].y));
                        acc4.x += v * a.x; acc4.y += v * a.y;
                        acc4.z += v * b.x; acc4.w += v * b.y;
                    }
                }
                for (; j < t; ++j) {
                    int2 ea = __ldg(&g_edges[j]);
                    uint2 ua = x2[(size_t)ea.x * 32 + lane];
                    float va = __int_as_float(ea.y);
                    float2 a = __half22float2(*reinterpret_cast<__half2*>(&ua.x));
                    float2 b = __half22float2(*reinterpret_cast<__half2*>(&ua.y));
                    acc4.x += va * a.x; acc4.y += va * a.y;
                    acc4.z += va * b.x; acc4.w += va * b.y;
                }
            }
            __half2 h0 = __float22half2_rn(make_float2(acc4.x, acc4.y));
            __half2 h1 = __float22half2_rn(make_float2(acc4.z, acc4.w));
            *reinterpret_cast<uint2*>(Asm + row * SHH + lane * 4) = make_uint2(
                *reinterpret_cast<uint32_t*>(&h0), *reinterpret_cast<uint32_t*>(&h1));
        }
    }

    float acc[2][8][4];
#pragma unroll
    for (int mt = 0; mt < 2; ++mt)
#pragma unroll
        for (int nt = 0; nt < 8; ++nt)
#pragma unroll
            for (int i = 0; i < 4; ++i) acc[mt][nt][i] = 0.f;

    // ---- layer 1: Asm @ W1 (A in smem at stride SHH) ----
#pragma unroll 1
    for (int kc = 0; kc < 2; ++kc) {
        if (kc < 1) cp_wait<1>(); else cp_wait<0>();
        __syncthreads();   // publishes Asm (kc=0) and Bb chunk
        mma_chunk16(Asm, SHH, kc * BK2, Bb[kc], m_base, n_base, g, tig, acc);
        __syncthreads();
    }

    cpB16(W2t, 0, Bb[0], tid);
    cp_commit();

    // ---- epilogue 1: relu(acc + b1) -> Hs ----
#pragma unroll
    for (int nt = 0; nt < 8; ++nt) {
        int col = n_base + nt * 8 + 2 * tig;
        float bx = __ldg(&b1[col]);
        float by = __ldg(&b1[col + 1]);
#pragma unroll
        for (int mt = 0; mt < 2; ++mt) {
#pragma unroll
            for (int h = 0; h < 2; ++h) {
                int row = m_base + mt * 16 + g + h * 8;
                float tx = fmaxf(acc[mt][nt][2 * h]     + bx, 0.f);
                float ty = fmaxf(acc[mt][nt][2 * h + 1] + by, 0.f);
                *reinterpret_cast<__half2*>(Hs + row * SHH + col) =
                    __float22half2_rn(make_float2(tx, ty));
                acc[mt][nt][2 * h] = 0.f;
                acc[mt][nt][2 * h + 1] = 0.f;
            }
        }
    }
    __syncthreads();

    // ---- layer 2: Hs @ W2 ----
#pragma unroll 1
    for (int kc = 0; kc < 2; ++kc) {
        if (kc < 1) {
            cpB16(W2t, BK2, Bb[1], tid);
            cp_commit();
            cp_wait<1>();
        } else {
            cp_wait<0>();
        }
        __syncthreads();
        mma_chunk16(Hs, SHH, kc * BK2, Bb[kc & 1], m_base, n_base, g, tig, acc);
        __syncthreads();
    }

    // ---- epilogue 2: fp16 out ----
#pragma unroll
    for (int nt = 0; nt < 8; ++nt) {
        int col = n_base + nt * 8 + 2 * tig;
        float2 bb = make_float2(__ldg(&b2[col]), __ldg(&b2[col + 1]));
#pragma unroll
        for (int mt = 0; mt < 2; ++mt) {
#pragma unroll
            for (int h = 0; h < 2; ++h) {
                int row = row0 + m_base + mt * 16 + g + h * 8;
                if (row >= Nrows) continue;
                float vx = acc[mt][nt][2 * h]     + bb.x;
                float vy = acc[mt][nt][2 * h + 1] + bb.y;
                *reinterpret_cast<__half2*>(&OH[(size_t)row * D + col]) =
                    __float22half2_rn(make_float2(vx, vy));
            }
        }
    }
}

// ===========================================================================
// Merged z/r gate kernel (gridDim.y = 2), fp16 GEMMs (R12-proven).
// ===========================================================================
__global__ void __launch_bounds__(THREADS, 2)
gate01_mma_kernel(const __half* __restrict__ out_, const __half* __restrict__ xh_,
                  const __half* __restrict__ wh,
                  const float* __restrict__ bu1, const float* __restrict__ bu2,
                  const float* __restrict__ br1, const float* __restrict__ br2,
                  int Nrows)
{
    __shared__ __half smA[2 * ABUF_H];
    __shared__ __half smB[2 * BBUF_H];

    int mode = blockIdx.y;
    const __half* Wa = wh + (size_t)(4 + 2 * mode) * D * D;
    const __half* Wb = wh + (size_t)(5 + 2 * mode) * D * D;
    const float* ba = mode ? br1 : bu1;
    const float* bb_ = mode ? br2 : bu2;

    int tid  = threadIdx.x;
    int warp = tid >> 5;
    int lane = tid & 31;
    int g    = lane >> 2;
    int tig  = lane & 3;
    int m_base = (warp >> 1) * 32;
    int n_base = (warp & 1) * 64;
    int row0 = blockIdx.x * 128;

    float acc[2][8][4];
#pragma unroll
    for (int mt = 0; mt < 2; ++mt)
#pragma unroll
        for (int nt = 0; nt < 8; ++nt)
#pragma unroll
            for (int i = 0; i < 4; ++i) acc[mt][nt][i] = 0.f;

    dual_gemm_h(out_, Wa, xh_, Wb, smA, smB, row0, Nrows, tid,
                m_base, n_base, g, tig, acc);

    const float2* x2 = reinterpret_cast<const float2*>(g_x);
#pragma unroll
    for (int nt = 0; nt < 8; ++nt) {
        int col = n_base + nt * 8 + 2 * tig;
        float2 bsum;
        bsum.x = __ldg(&ba[col])     + __ldg(&bb_[col]);
        bsum.y = __ldg(&ba[col + 1]) + __ldg(&bb_[col + 1]);
#pragma unroll
        for (int mt = 0; mt < 2; ++mt) {
#pragma unroll
            for (int h = 0; h < 2; ++h) {
                int row = row0 + m_base + mt * 16 + g + h * 8;
                if (row >= Nrows) continue;
                float sx = sigf(acc[mt][nt][2 * h]     + bsum.x);
                float sy = sigf(acc[mt][nt][2 * h + 1] + bsum.y);
                size_t p = (size_t)row * 64 + (col >> 1);
                if (mode == 0) {
                    reinterpret_cast<float2*>(g_z)[p] = make_float2(sx, sy);
                } else {
                    float2 xv = x2[p];
                    *reinterpret_cast<__half2*>(&g_rxh[(size_t)row * D + col]) =
                        __float22half2_rn(make_float2(sx * xv.x, sy * xv.y));
                }
            }
        }
    }
}

// Final gate: O = (1-z)*x + z*tanh(out@Wo1 + rx@Wo2 + bo1 + bo2)
__global__ void __launch_bounds__(THREADS, 2)
gate2_mma_kernel(const __half* __restrict__ out_, const __half* __restrict__ rx_,
                 const __half* __restrict__ wh,
                 const float* __restrict__ bo1, const float* __restrict__ bo2,
                 float* __restrict__ O, int Nrows)
{
    __shared__ __half smA[2 * ABUF_H];
    __shared__ __half smB[2 * BBUF_H];

    const __half* Wa = wh + (size_t)8 * D * D;
    const __half* Wb = wh + (size_t)9 * D * D;

    int tid  = threadIdx.x;
    int warp = tid >> 5;
    int lane = tid & 31;
    int g    = lane >> 2;
    int tig  = lane & 3;
    int m_base = (warp >> 1) * 32;
    int n_base = (warp & 1) * 64;
    int row0 = blockIdx.x * 128;

    float acc[2][8][4];
#pragma unroll
    for (int mt = 0; mt < 2; ++mt)
#pragma unroll
        for (int nt = 0; nt < 8; ++nt)
#pragma unroll
            for (int i = 0; i < 4; ++i) acc[mt][nt][i] = 0.f;

    dual_gemm_h(out_, Wa, rx_, Wb, smA, smB, row0, Nrows, tid,
                m_base, n_base, g, tig, acc);

    const float2* x2 = reinterpret_cast<const float2*>(g_x);
    const float2* z2 = reinterpret_cast<const float2*>(g_z);
#pragma unroll
    for (int nt = 0; nt < 8; ++nt) {
        int col = n_base + nt * 8 + 2 * tig;
        float2 bsum;
        bsum.x = __ldg(&bo1[col])     + __ldg(&bo2[col]);
        bsum.y = __ldg(&bo1[col + 1]) + __ldg(&bo2[col + 1]);
#pragma unroll
        for (int mt = 0; mt < 2; ++mt) {
#pragma unroll
            for (int h = 0; h < 2; ++h) {
                int row = row0 + m_base + mt * 16 + g + h * 8;
                if (row >= Nrows) continue;
                float tx = acc[mt][nt][2 * h]     + bsum.x;
                float ty = acc[mt][nt][2 * h + 1] + bsum.y;
                size_t p = (size_t)row * 64 + (col >> 1);
                float2 xv = x2[p];
                float2 zv = z2[p];
                float2 o;
                o.x = (1.f - zv.x) * xv.x + zv.x * tanhf(tx);
                o.y = (1.f - zv.y) * xv.y + zv.y * tanhf(ty);
                reinterpret_cast<float2*>(O)[p] = o;
            }
        }
    }
}

// ===========================================================================
// Conversions
// ===========================================================================
__global__ void cvtw_kernel(const float* w0, const float* w1, const float* w2,
                            const float* w3, const float* w4, const float* w5,
                            const float* w6, const float* w7, const float* w8,
                            const float* w9, __half* dst)
{
    const float* ws[10] = {w0, w1, w2, w3, w4, w5, w6, w7, w8, w9};
    const float* w = ws[blockIdx.y];
    int i = blockIdx.x * 256 + threadIdx.x;
    int n = i >> 7;
    int k = i & 127;
    dst[(size_t)blockIdx.y * D * D + i] = __float2half_rn(w[(size_t)k * D + n]);
}

__global__ void cvtx_kernel(const float* __restrict__ src, __half* __restrict__ dst, int n4)
{
    int i = blockIdx.x * blockDim.x + threadIdx.x;
    if (i < n4) {
        float4 v = reinterpret_cast<const float4*>(src)[i];
        __half2 h0 = __float22half2_rn(make_float2(v.x, v.y));
        __half2 h1 = __float22half2_rn(make_float2(v.z, v.w));
        reinterpret_cast<uint2*>(dst)[i] = make_uint2(
            *reinterpret_cast<uint32_t*>(&h0), *reinterpret_cast<uint32_t*>(&h1));
    }
}

// ===========================================================================
// CSR build
// ===========================================================================
__global__ void count_kernel(const int* __restrict__ rows, int E)
{
    int e = blockIdx.x * blockDim.x + threadIdx.x;
    if (e < E) atomicAdd(&g_cnt[rows[e]], 1);
}

__global__ void scan_kernel(int Nn)
{
    __shared__ int warp_tot[32];
    int t = threadIdx.x;
    int lane = t & 31, w = t >> 5;
    int C = (Nn + 1023) / 1024;
    int lo = t * C;
    int hi = min(lo + C, Nn);

    int sum = 0;
    for (int i = lo; i < hi; ++i) sum += g_cnt[i];

    int v = sum;
#pragma unroll
    for (int o = 1; o < 32; o <<= 1) {
        int u = __shfl_up_sync(0xffffffffu, v, o);
        if (lane >= o) v += u;
    }
    if (lane == 31) warp_tot[w] = v;
    __syncthreads();
    if (w == 0) {
        int tv = warp_tot[lane];
#pragma unroll
        for (int o = 1; o < 32; o <<= 1) {
            int u = __shfl_up_sync(0xffffffffu, tv, o);
            if (lane >= o) tv += u;
        }
        warp_tot[lane] = tv;
    }
    __syncthreads();
    int incl = v + (w > 0 ? warp_tot[w - 1] : 0);
    int run = incl - sum;

    for (int i = lo; i < hi; ++i) {
        int c = g_cnt[i];
        g_start[i] = run;
        g_cur[i] = run;
        run += c;
    }
    if (t == 1023) g_start[Nn] = run;
}

__global__ void fill_kernel(const int* __restrict__ rows, const int* __restrict__ cols,
                            const float* __restrict__ vals, int E)
{
    int e = blockIdx.x * blockDim.x + threadIdx.x;
    if (e < E) {
        int r = rows[e];
        int pos = atomicAdd(&g_cur[r], 1);
        g_edges[pos] = make_int2(cols[e], __float_as_int(vals[e]));
    }
}

// ---------------------------------------------------------------------------
extern "C" void kernel_launch(void* const* d_in, const int* in_sizes, int n_in,
                              void* d_out, int out_size)
{
    const float* x_in  = (const float*)d_in[0];
    const int*   rows  = (const int*)  d_in[1];
    const int*   cols  = (const int*)  d_in[2];
    const float* vals  = (const float*)d_in[3];
    const float* m1_W1 = (const float*)d_in[4];
    const float* m1_b1 = (const float*)d_in[5];
    const float* m1_W2 = (const float*)d_in[6];
    const float* m1_b2 = (const float*)d_in[7];
    const float* m2_W1 = (const float*)d_in[8];
    const float* m2_b1 = (const float*)d_in[9];
    const float* m2_W2 = (const float*)d_in[10];
    const float* m2_b2 = (const float*)d_in[11];
    const float* Wu1   = (const float*)d_in[12];
    const float* bu1   = (const float*)d_in[13];
    const float* Wu2   = (const float*)d_in[14];
    const float* bu2   = (const float*)d_in[15];
    const float* Wr1   = (const float*)d_in[16];
    const float* br1   = (const float*)d_in[17];
    const float* Wr2   = (const float*)d_in[18];
    const float* br2   = (const float*)d_in[19];
    const float* Wo1   = (const float*)d_in[20];
    const float* bo1   = (const float*)d_in[21];
    const float* Wo2   = (const float*)d_in[22];
    const float* bo2   = (const float*)d_in[23];

    int N = in_sizes[0] / D;
    int E = in_sizes[1];

    float *px;
    __half *pxh, *pxinh, *pouth, *prxh, *pwh;
    int* pcnt;
    cudaGetSymbolAddress((void**)&px,    g_x);
    cudaGetSymbolAddress((void**)&pxh,   g_xh);
    cudaGetSymbolAddress((void**)&pxinh, g_xinh);
    cudaGetSymbolAddress((void**)&pouth, g_outh);
    cudaGetSymbolAddress((void**)&prxh,  g_rxh);
    cudaGetSymbolAddress((void**)&pwh,   g_wh);
    cudaGetSymbolAddress((void**)&pcnt,  g_cnt);

    static cudaStream_t s_side = nullptr;
    static cudaEvent_t ev_fork = nullptr, ev_join = nullptr;
    if (!s_side) {
        cudaStreamCreateWithFlags(&s_side, cudaStreamNonBlocking);
        cudaEventCreateWithFlags(&ev_fork, cudaEventDisableTiming);
        cudaEventCreateWithFlags(&ev_join, cudaEventDisableTiming);
    }

    int smem_mlp1 = (2 * ABUF_H + 2 * BBUF_H + 128 * SHH) * (int)sizeof(__half);    // 108544 B
    int smem_mlp2 = (FULLA_H + 2 * BBUF_H + 128 * SHH) * (int)sizeof(__half);       // 106496 B
    cudaFuncSetAttribute(mlp1_mma_kernel,    cudaFuncAttributeMaxDynamicSharedMemorySize, smem_mlp1);
    cudaFuncSetAttribute(mlp2agg_mma_kernel, cudaFuncAttributeMaxDynamicSharedMemorySize, smem_mlp2);

    int nblk = (N + 127) / 128;
    int eblk = (E + 255) / 256;
    int n4 = N * D / 4;

    // ---- fork: CSR build on side stream ----
    cudaEventRecord(ev_fork, 0);
    cudaStreamWaitEvent(s_side, ev_fork, 0);
    cudaMemsetAsync(pcnt, 0, (size_t)N * sizeof(int), s_side);
    count_kernel<<<eblk, 256, 0, s_side>>>(rows, E);
    scan_kernel<<<1, 1024, 0, s_side>>>(N);
    fill_kernel<<<eblk, 256, 0, s_side>>>(rows, cols, vals, E);
    cudaEventRecord(ev_join, s_side);

    // ---- main: conversions, then pipeline ----
    dim3 wgrid(64, 10);
    cvtw_kernel<<<wgrid, 256>>>(m1_W1, m1_W2, m2_W1, m2_W2, Wu1, Wu2, Wr1, Wr2, Wo1, Wo2, pwh);
    cvtx_kernel<<<(n4 + 255) / 256, 256>>>(x_in, pxinh, n4);

    mlp1_mma_kernel<<<nblk, THREADS, smem_mlp1>>>(
        pxinh, pwh + 0 * D * D, m1_b1, pwh + 1 * D * D, m1_b2, px, pxh, N);

    cudaStreamWaitEvent(0, ev_join, 0);
    mlp2agg_mma_kernel<<<nblk, THREADS, smem_mlp2>>>(
        pxh, pwh + 2 * D * D, m2_b1, pwh + 3 * D * D, m2_b2, pouth, N);

    dim3 grid01(nblk, 2);
    gate01_mma_kernel<<<grid01, THREADS>>>(pouth, pxh, pwh, bu1, bu2, br1, br2, N);
    gate2_mma_kernel<<<nblk, THREADS>>>(pouth, prxh, pwh, bo1, bo2, (float*)d_out, N);
}